// round 2
// baseline (speedup 1.0000x reference)
#include <cuda_runtime.h>

#define NROWS 1024
#define EMB   256

__device__ __forceinline__ int lower_bound_i(const int* __restrict__ a, int n, int key) {
    int lo = 0, hi = n;
    while (lo < hi) { int mid = (lo + hi) >> 1; if (a[mid] < key) lo = mid + 1; else hi = mid; }
    return lo;
}
__device__ __forceinline__ int upper_bound_i(const int* __restrict__ a, int n, int key) {
    int lo = 0, hi = n;
    while (lo < hi) { int mid = (lo + hi) >> 1; if (a[mid] <= key) lo = mid + 1; else hi = mid; }
    return lo;
}

// One CTA per row i. Phase 1: zero the full row of out_pred and out_mask
// (vectorized, 256 float4 per row per array). Phase 2: compute only the
// same-graph contiguous column segment [lo, hi): warp-per-j, lane owns 8 dims.
__global__ __launch_bounds__(256) void distmax_rows(
    const float* __restrict__ xs, const int* __restrict__ batch,
    const float* __restrict__ w, const float* __restrict__ bptr,
    float* __restrict__ out_pred, float* __restrict__ out_mask)
{
    const int i = blockIdx.x;
    const int t = threadIdx.x;
    __shared__ int s_lo, s_hi;
    if (t == 0) {
        int bi = batch[i];
        s_lo = lower_bound_i(batch, NROWS, bi);
        s_hi = upper_bound_i(batch, NROWS, bi);
    }

    // Phase 1: zero both output rows (1024 floats each) with STG.128.
    const float4 z = make_float4(0.f, 0.f, 0.f, 0.f);
    float4* pr = reinterpret_cast<float4*>(out_pred + (size_t)i * NROWS);
    float4* mr = reinterpret_cast<float4*>(out_mask + (size_t)i * NROWS);
    pr[t] = z;
    mr[t] = z;
    __syncthreads();

    const int lo = s_lo, hi = s_hi;
    const float bias = __ldg(bptr);
    const int lane = t & 31;
    const int wid  = t >> 5;

    // Preload this lane's 8-dim slice of x_i and w (dims [lane*8, lane*8+8)).
    const float4* xi4 = reinterpret_cast<const float4*>(xs + (size_t)i * EMB);
    const float4* w4  = reinterpret_cast<const float4*>(w);
    const float4 xi0 = xi4[lane * 2], xi1 = xi4[lane * 2 + 1];
    const float4 w0  = w4 [lane * 2], w1  = w4 [lane * 2 + 1];

    // Phase 2: warp-per-column over the same-graph segment.
    for (int j = lo + wid; j < hi; j += 8) {
        const float4* xj4 = reinterpret_cast<const float4*>(xs + (size_t)j * EMB);
        const float4 xj0 = xj4[lane * 2], xj1 = xj4[lane * 2 + 1];
        float acc;
        acc  = fmaxf(xi0.x, xj0.x) * w0.x;
        acc += fmaxf(xi0.y, xj0.y) * w0.y;
        acc += fmaxf(xi0.z, xj0.z) * w0.z;
        acc += fmaxf(xi0.w, xj0.w) * w0.w;
        acc += fmaxf(xi1.x, xj1.x) * w1.x;
        acc += fmaxf(xi1.y, xj1.y) * w1.y;
        acc += fmaxf(xi1.z, xj1.z) * w1.z;
        acc += fmaxf(xi1.w, xj1.w) * w1.w;
        #pragma unroll
        for (int o = 16; o; o >>= 1) acc += __shfl_xor_sync(0xffffffffu, acc, o);
        if (lane == 0 && j != i) {
            out_pred[(size_t)i * NROWS + j] = fmaxf(acc + bias, 0.0f);
            out_mask[(size_t)i * NROWS + j] = 1.0f;
        }
    }
}

// count = sum over rows of (group_size - 1). Exact integer -> f32.
__global__ __launch_bounds__(1024) void distmax_count(
    const int* __restrict__ batch, float* __restrict__ out_count)
{
    const int i = threadIdx.x;
    int bi = batch[i];
    int lo = lower_bound_i(batch, NROWS, bi);
    int hi = upper_bound_i(batch, NROWS, bi);
    int c = hi - lo - 1;
    #pragma unroll
    for (int o = 16; o; o >>= 1) c += __shfl_xor_sync(0xffffffffu, c, o);
    __shared__ int ws[32];
    if ((i & 31) == 0) ws[i >> 5] = c;
    __syncthreads();
    if (i < 32) {
        int v = ws[i];
        #pragma unroll
        for (int o = 16; o; o >>= 1) v += __shfl_xor_sync(0xffffffffu, v, o);
        if (i == 0) out_count[0] = (float)v;
    }
}

extern "C" void kernel_launch(void* const* d_in, const int* in_sizes, int n_in,
                              void* d_out, int out_size)
{
    const float* xs    = (const float*)d_in[0];  // [1024, 256] f32
    const int*   batch = (const int*)d_in[1];    // [1024] int32 (sorted; jax demotes int64)
    const float* w     = (const float*)d_in[2];  // [256] f32
    const float* b     = (const float*)d_in[3];  // [1] f32

    float* out       = (float*)d_out;
    float* out_pred  = out;                              // [1024*1024]
    float* out_mask  = out + (size_t)NROWS * NROWS;      // [1024*1024]
    float* out_count = out + 2 * (size_t)NROWS * NROWS;  // [1]

    distmax_rows<<<NROWS, 256>>>(xs, batch, w, b, out_pred, out_mask);
    distmax_count<<<1, 1024>>>(batch, out_count);
}

// round 3
// speedup vs baseline: 1.1356x; 1.1356x over previous
#include <cuda_runtime.h>

#define NROWS 1024
#define EMB   256

__device__ __forceinline__ int lower_bound_i(const int* __restrict__ a, int n, int key) {
    int lo = 0, hi = n;
    while (lo < hi) { int mid = (lo + hi) >> 1; if (a[mid] < key) lo = mid + 1; else hi = mid; }
    return lo;
}
__device__ __forceinline__ int upper_bound_i(const int* __restrict__ a, int n, int key) {
    int lo = 0, hi = n;
    while (lo < hi) { int mid = (lo + hi) >> 1; if (a[mid] <= key) lo = mid + 1; else hi = mid; }
    return lo;
}

// One CTA per row i.
// Phase 1: zero the full rows of out_pred and out_mask (256 STG.128 per array).
// Phase 2: compute the same-graph contiguous column segment [lo, hi):
//          warp-per-j, each lane owns 8 contiguous dims, shfl-butterfly reduce.
// CTA 0 additionally computes count = sum_i (group_size_i - 1) from an smem
// copy of batch (integer-exact, deterministic) — fusing away the 2nd launch.
__global__ __launch_bounds__(256) void distmax_fused(
    const float* __restrict__ xs, const int* __restrict__ batch,
    const float* __restrict__ w, const float* __restrict__ bptr,
    float* __restrict__ out_pred, float* __restrict__ out_mask,
    float* __restrict__ out_count)
{
    const int i = blockIdx.x;
    const int t = threadIdx.x;
    __shared__ int s_lo, s_hi;
    if (t == 0) {
        int bi = batch[i];
        s_lo = lower_bound_i(batch, NROWS, bi);
        s_hi = upper_bound_i(batch, NROWS, bi);
    }

    // Phase 1: zero both output rows (1024 floats each) with STG.128.
    const float4 z = make_float4(0.f, 0.f, 0.f, 0.f);
    float4* pr = reinterpret_cast<float4*>(out_pred + (size_t)i * NROWS);
    float4* mr = reinterpret_cast<float4*>(out_mask + (size_t)i * NROWS);
    pr[t] = z;
    mr[t] = z;
    __syncthreads();

    const int lo = s_lo, hi = s_hi;
    const float bias = __ldg(bptr);
    const int lane = t & 31;
    const int wid  = t >> 5;

    // Preload this lane's 8-dim slice of x_i and w (dims [lane*8, lane*8+8)).
    const float4* xi4 = reinterpret_cast<const float4*>(xs + (size_t)i * EMB);
    const float4* w4  = reinterpret_cast<const float4*>(w);
    const float4 xi0 = xi4[lane * 2], xi1 = xi4[lane * 2 + 1];
    const float4 w0  = w4 [lane * 2], w1  = w4 [lane * 2 + 1];

    // Phase 2: warp-per-column over the same-graph segment.
    for (int j = lo + wid; j < hi; j += 8) {
        const float4* xj4 = reinterpret_cast<const float4*>(xs + (size_t)j * EMB);
        const float4 xj0 = xj4[lane * 2], xj1 = xj4[lane * 2 + 1];
        float acc;
        acc  = fmaxf(xi0.x, xj0.x) * w0.x;
        acc += fmaxf(xi0.y, xj0.y) * w0.y;
        acc += fmaxf(xi0.z, xj0.z) * w0.z;
        acc += fmaxf(xi0.w, xj0.w) * w0.w;
        acc += fmaxf(xi1.x, xj1.x) * w1.x;
        acc += fmaxf(xi1.y, xj1.y) * w1.y;
        acc += fmaxf(xi1.z, xj1.z) * w1.z;
        acc += fmaxf(xi1.w, xj1.w) * w1.w;
        #pragma unroll
        for (int o = 16; o; o >>= 1) acc += __shfl_xor_sync(0xffffffffu, acc, o);
        if (lane == 0 && j != i) {
            out_pred[(size_t)i * NROWS + j] = fmaxf(acc + bias, 0.0f);
            out_mask[(size_t)i * NROWS + j] = 1.0f;
        }
    }

    // CTA 0 only: count = sum over rows of (group_size - 1), via smem batch.
    if (i == 0) {
        __shared__ int sb[NROWS];
        __shared__ int ws[8];
        #pragma unroll
        for (int k = 0; k < 4; k++) sb[t + k * 256] = batch[t + k * 256];
        __syncthreads();
        int c = 0;
        #pragma unroll
        for (int k = 0; k < 4; k++) {
            int r  = t + k * 256;
            int br = sb[r];
            int l2 = lower_bound_i(sb, NROWS, br);
            int h2 = upper_bound_i(sb, NROWS, br);
            c += h2 - l2 - 1;
        }
        #pragma unroll
        for (int o = 16; o; o >>= 1) c += __shfl_xor_sync(0xffffffffu, c, o);
        if (lane == 0) ws[wid] = c;
        __syncthreads();
        if (t == 0) {
            int v = 0;
            #pragma unroll
            for (int u = 0; u < 8; u++) v += ws[u];
            out_count[0] = (float)v;
        }
    }
}

extern "C" void kernel_launch(void* const* d_in, const int* in_sizes, int n_in,
                              void* d_out, int out_size)
{
    const float* xs    = (const float*)d_in[0];  // [1024, 256] f32
    const int*   batch = (const int*)d_in[1];    // [1024] int32 (sorted)
    const float* w     = (const float*)d_in[2];  // [256] f32
    const float* b     = (const float*)d_in[3];  // [1] f32

    float* out       = (float*)d_out;
    float* out_pred  = out;                              // [1024*1024]
    float* out_mask  = out + (size_t)NROWS * NROWS;      // [1024*1024]
    float* out_count = out + 2 * (size_t)NROWS * NROWS;  // [1]

    distmax_fused<<<NROWS, 256>>>(xs, batch, w, b, out_pred, out_mask, out_count);
}

// round 4
// speedup vs baseline: 1.2885x; 1.1346x over previous
#include <cuda_runtime.h>

#define NROWS 1024
#define EMB   256

// Row CTAs (blockIdx.x < NROWS): one CTA per row i, 8 warps, NO block sync.
//   Each warp independently: (1) computes the same-graph segment bounds
//   [lo,hi) by parallel counting over the sorted batch array, (2) zeroes its
//   share of the columns OUTSIDE [lo,hi), (3) computes every column inside
//   [lo,hi) (diagonal written as 0) warp-per-j with 2-way unrolled shfl chains.
// Count CTA (blockIdx.x == NROWS): 32-bin smem histogram of batch;
//   count = sum_g h_g^2 - N (integer exact).
__global__ __launch_bounds__(256) void distmax_fused(
    const float* __restrict__ xs, const int* __restrict__ batch,
    const float* __restrict__ w, const float* __restrict__ bptr,
    float* __restrict__ out_pred, float* __restrict__ out_mask,
    float* __restrict__ out_count)
{
    const int t    = threadIdx.x;
    const int lane = t & 31;
    const int wid  = t >> 5;

    // ---- dedicated count CTA ----
    if (blockIdx.x == NROWS) {
        __shared__ int h[32];
        if (t < 32) h[t] = 0;
        __syncthreads();
        int4 v = reinterpret_cast<const int4*>(batch)[t];  // 256*4 = 1024 elems
        atomicAdd(&h[v.x], 1);
        atomicAdd(&h[v.y], 1);
        atomicAdd(&h[v.z], 1);
        atomicAdd(&h[v.w], 1);
        __syncthreads();
        if (t < 32) {
            int c = h[t] * h[t];
            #pragma unroll
            for (int o = 16; o; o >>= 1) c += __shfl_xor_sync(0xffffffffu, c, o);
            if (t == 0) out_count[0] = (float)(c - NROWS);
        }
        return;
    }

    const int i = blockIdx.x;

    // ---- per-warp segment bounds: lo = #(batch < bi), hi = #(batch <= bi) ----
    const int bi = batch[i];
    int cnt_lt = 0, cnt_le = 0;
    const int4* b4 = reinterpret_cast<const int4*>(batch);
    #pragma unroll
    for (int k = 0; k < 8; k++) {
        int4 v = b4[k * 32 + lane];  // coalesced; whole array per warp
        cnt_lt += (v.x <  bi) + (v.y <  bi) + (v.z <  bi) + (v.w <  bi);
        cnt_le += (v.x <= bi) + (v.y <= bi) + (v.z <= bi) + (v.w <= bi);
    }
    #pragma unroll
    for (int o = 16; o; o >>= 1) {
        cnt_lt += __shfl_xor_sync(0xffffffffu, cnt_lt, o);
        cnt_le += __shfl_xor_sync(0xffffffffu, cnt_le, o);
    }
    const int lo = cnt_lt, hi = cnt_le;

    const size_t rowoff = (size_t)i * NROWS;
    float* __restrict__ prow = out_pred + rowoff;
    float* __restrict__ mrow = out_mask + rowoff;

    // ---- zero phase: only columns outside [lo, hi) ----
    {
        const int c0 = t * 4;
        if (c0 + 4 <= lo || c0 >= hi) {
            const float4 z = make_float4(0.f, 0.f, 0.f, 0.f);
            reinterpret_cast<float4*>(prow)[t] = z;
            reinterpret_cast<float4*>(mrow)[t] = z;
        } else if (c0 < lo || c0 + 4 > hi) {
            #pragma unroll
            for (int e = 0; e < 4; e++) {
                int c = c0 + e;
                if (c < lo || c >= hi) { prow[c] = 0.f; mrow[c] = 0.f; }
            }
        }
        // fully inside [lo,hi): compute phase writes it
    }

    // ---- compute phase: warp-per-j over [lo, hi), 2-way unrolled ----
    const float bias = __ldg(bptr);
    const float4* xi4 = reinterpret_cast<const float4*>(xs + (size_t)i * EMB);
    const float4* w4  = reinterpret_cast<const float4*>(w);
    const float4 xi0 = xi4[lane * 2], xi1 = xi4[lane * 2 + 1];
    const float4 w0  = w4 [lane * 2], w1  = w4 [lane * 2 + 1];

    for (int j = lo + wid; j < hi; j += 16) {
        const int  j2   = j + 8;
        const bool has2 = (j2 < hi);

        const float4* xj4 = reinterpret_cast<const float4*>(xs + (size_t)j * EMB);
        const float4 a0 = xj4[lane * 2], a1 = xj4[lane * 2 + 1];
        float acc0;
        acc0  = fmaxf(xi0.x, a0.x) * w0.x;
        acc0 += fmaxf(xi0.y, a0.y) * w0.y;
        acc0 += fmaxf(xi0.z, a0.z) * w0.z;
        acc0 += fmaxf(xi0.w, a0.w) * w0.w;
        acc0 += fmaxf(xi1.x, a1.x) * w1.x;
        acc0 += fmaxf(xi1.y, a1.y) * w1.y;
        acc0 += fmaxf(xi1.z, a1.z) * w1.z;
        acc0 += fmaxf(xi1.w, a1.w) * w1.w;

        float acc1 = 0.f;
        if (has2) {
            const float4* xk4 = reinterpret_cast<const float4*>(xs + (size_t)j2 * EMB);
            const float4 c0v = xk4[lane * 2], c1v = xk4[lane * 2 + 1];
            acc1  = fmaxf(xi0.x, c0v.x) * w0.x;
            acc1 += fmaxf(xi0.y, c0v.y) * w0.y;
            acc1 += fmaxf(xi0.z, c0v.z) * w0.z;
            acc1 += fmaxf(xi0.w, c0v.w) * w0.w;
            acc1 += fmaxf(xi1.x, c1v.x) * w1.x;
            acc1 += fmaxf(xi1.y, c1v.y) * w1.y;
            acc1 += fmaxf(xi1.z, c1v.z) * w1.z;
            acc1 += fmaxf(xi1.w, c1v.w) * w1.w;
        }

        #pragma unroll
        for (int o = 16; o; o >>= 1) {
            acc0 += __shfl_xor_sync(0xffffffffu, acc0, o);
            acc1 += __shfl_xor_sync(0xffffffffu, acc1, o);
        }

        if (lane == 0) {
            prow[j] = (j == i) ? 0.f : fmaxf(acc0 + bias, 0.f);
            mrow[j] = (j == i) ? 0.f : 1.f;
            if (has2) {
                prow[j2] = (j2 == i) ? 0.f : fmaxf(acc1 + bias, 0.f);
                mrow[j2] = (j2 == i) ? 0.f : 1.f;
            }
        }
    }
}

extern "C" void kernel_launch(void* const* d_in, const int* in_sizes, int n_in,
                              void* d_out, int out_size)
{
    const float* xs    = (const float*)d_in[0];  // [1024, 256] f32
    const int*   batch = (const int*)d_in[1];    // [1024] int32 (sorted, ids in [0,32))
    const float* w     = (const float*)d_in[2];  // [256] f32
    const float* b     = (const float*)d_in[3];  // [1] f32

    float* out       = (float*)d_out;
    float* out_pred  = out;                              // [1024*1024]
    float* out_mask  = out + (size_t)NROWS * NROWS;      // [1024*1024]
    float* out_count = out + 2 * (size_t)NROWS * NROWS;  // [1]

    distmax_fused<<<NROWS + 1, 256>>>(xs, batch, w, b, out_pred, out_mask, out_count);
}

// round 5
// speedup vs baseline: 1.3400x; 1.0400x over previous
#include <cuda_runtime.h>

#define NROWS 1024
#define EMB   256

// Row CTAs (blockIdx.x < NROWS): one CTA per row i, 8 warps.
//   (a) all threads zero the full pred/mask rows (2x STG.128 each),
//   (b) warp 0 alone computes the same-graph segment [lo,hi) by parallel
//       counting over sorted batch (once per CTA, not per warp),
//   (c) __syncthreads (orders zero-stores, publishes bounds),
//   (d) warps compute columns in [lo,hi) 4-way unrolled, overwriting the
//       interior (diagonal written as 0).
// Count CTA (blockIdx.x == NROWS): 32-bin histogram; count = sum h_g^2 - N.
__global__ __launch_bounds__(256) void distmax_fused(
    const float* __restrict__ xs, const int* __restrict__ batch,
    const float* __restrict__ w, const float* __restrict__ bptr,
    float* __restrict__ out_pred, float* __restrict__ out_mask,
    float* __restrict__ out_count)
{
    const int t    = threadIdx.x;
    const int lane = t & 31;
    const int wid  = t >> 5;

    // ---- dedicated count CTA ----
    if (blockIdx.x == NROWS) {
        __shared__ int h[32];
        if (t < 32) h[t] = 0;
        __syncthreads();
        int4 v = reinterpret_cast<const int4*>(batch)[t];  // 256*4 = 1024 elems
        atomicAdd(&h[v.x], 1);
        atomicAdd(&h[v.y], 1);
        atomicAdd(&h[v.z], 1);
        atomicAdd(&h[v.w], 1);
        __syncthreads();
        if (t < 32) {
            int c = h[t] * h[t];
            #pragma unroll
            for (int o = 16; o; o >>= 1) c += __shfl_xor_sync(0xffffffffu, c, o);
            if (t == 0) out_count[0] = (float)(c - NROWS);
        }
        return;
    }

    const int i = blockIdx.x;
    const size_t rowoff = (size_t)i * NROWS;
    float* __restrict__ prow = out_pred + rowoff;
    float* __restrict__ mrow = out_mask + rowoff;

    __shared__ int s_lo, s_hi;

    // ---- (a) zero full rows ----
    const float4 z = make_float4(0.f, 0.f, 0.f, 0.f);
    reinterpret_cast<float4*>(prow)[t] = z;
    reinterpret_cast<float4*>(mrow)[t] = z;

    // ---- (b) warp 0: segment bounds by parallel counting ----
    if (wid == 0) {
        const int bi = batch[i];
        int cnt_lt = 0, cnt_le = 0;
        const int4* b4 = reinterpret_cast<const int4*>(batch);
        #pragma unroll
        for (int k = 0; k < 8; k++) {
            int4 v = b4[k * 32 + lane];
            cnt_lt += (v.x <  bi) + (v.y <  bi) + (v.z <  bi) + (v.w <  bi);
            cnt_le += (v.x <= bi) + (v.y <= bi) + (v.z <= bi) + (v.w <= bi);
        }
        #pragma unroll
        for (int o = 16; o; o >>= 1) {
            cnt_lt += __shfl_xor_sync(0xffffffffu, cnt_lt, o);
            cnt_le += __shfl_xor_sync(0xffffffffu, cnt_le, o);
        }
        if (lane == 0) { s_lo = cnt_lt; s_hi = cnt_le; }
    }

    // ---- (c) barrier: publish bounds + order the zero-stores ----
    __syncthreads();
    const int lo = s_lo, hi = s_hi;

    // ---- (d) compute phase: warp-per-j over [lo,hi), 4-way unrolled ----
    const float bias = __ldg(bptr);
    const float4* xi4 = reinterpret_cast<const float4*>(xs + (size_t)i * EMB);
    const float4* w4  = reinterpret_cast<const float4*>(w);
    const float4 xi0 = xi4[lane * 2], xi1 = xi4[lane * 2 + 1];
    const float4 w0  = w4 [lane * 2], w1  = w4 [lane * 2 + 1];

    for (int jb = lo + wid; jb < hi; jb += 32) {
        const int j0 = jb, j1 = jb + 8, j2 = jb + 16, j3 = jb + 24;
        const bool p1 = (j1 < hi), p2 = (j2 < hi), p3 = (j3 < hi);

        float acc0 = 0.f, acc1 = 0.f, acc2 = 0.f, acc3 = 0.f;

        // j0 always valid
        {
            const float4* xj = reinterpret_cast<const float4*>(xs + (size_t)j0 * EMB);
            const float4 a = xj[lane * 2], b = xj[lane * 2 + 1];
            acc0  = fmaxf(xi0.x, a.x) * w0.x;
            acc0 += fmaxf(xi0.y, a.y) * w0.y;
            acc0 += fmaxf(xi0.z, a.z) * w0.z;
            acc0 += fmaxf(xi0.w, a.w) * w0.w;
            acc0 += fmaxf(xi1.x, b.x) * w1.x;
            acc0 += fmaxf(xi1.y, b.y) * w1.y;
            acc0 += fmaxf(xi1.z, b.z) * w1.z;
            acc0 += fmaxf(xi1.w, b.w) * w1.w;
        }
        if (p1) {
            const float4* xj = reinterpret_cast<const float4*>(xs + (size_t)j1 * EMB);
            const float4 a = xj[lane * 2], b = xj[lane * 2 + 1];
            acc1  = fmaxf(xi0.x, a.x) * w0.x;
            acc1 += fmaxf(xi0.y, a.y) * w0.y;
            acc1 += fmaxf(xi0.z, a.z) * w0.z;
            acc1 += fmaxf(xi0.w, a.w) * w0.w;
            acc1 += fmaxf(xi1.x, b.x) * w1.x;
            acc1 += fmaxf(xi1.y, b.y) * w1.y;
            acc1 += fmaxf(xi1.z, b.z) * w1.z;
            acc1 += fmaxf(xi1.w, b.w) * w1.w;
        }
        if (p2) {
            const float4* xj = reinterpret_cast<const float4*>(xs + (size_t)j2 * EMB);
            const float4 a = xj[lane * 2], b = xj[lane * 2 + 1];
            acc2  = fmaxf(xi0.x, a.x) * w0.x;
            acc2 += fmaxf(xi0.y, a.y) * w0.y;
            acc2 += fmaxf(xi0.z, a.z) * w0.z;
            acc2 += fmaxf(xi0.w, a.w) * w0.w;
            acc2 += fmaxf(xi1.x, b.x) * w1.x;
            acc2 += fmaxf(xi1.y, b.y) * w1.y;
            acc2 += fmaxf(xi1.z, b.z) * w1.z;
            acc2 += fmaxf(xi1.w, b.w) * w1.w;
        }
        if (p3) {
            const float4* xj = reinterpret_cast<const float4*>(xs + (size_t)j3 * EMB);
            const float4 a = xj[lane * 2], b = xj[lane * 2 + 1];
            acc3  = fmaxf(xi0.x, a.x) * w0.x;
            acc3 += fmaxf(xi0.y, a.y) * w0.y;
            acc3 += fmaxf(xi0.z, a.z) * w0.z;
            acc3 += fmaxf(xi0.w, a.w) * w0.w;
            acc3 += fmaxf(xi1.x, b.x) * w1.x;
            acc3 += fmaxf(xi1.y, b.y) * w1.y;
            acc3 += fmaxf(xi1.z, b.z) * w1.z;
            acc3 += fmaxf(xi1.w, b.w) * w1.w;
        }

        #pragma unroll
        for (int o = 16; o; o >>= 1) {
            acc0 += __shfl_xor_sync(0xffffffffu, acc0, o);
            acc1 += __shfl_xor_sync(0xffffffffu, acc1, o);
            acc2 += __shfl_xor_sync(0xffffffffu, acc2, o);
            acc3 += __shfl_xor_sync(0xffffffffu, acc3, o);
        }

        if (lane == 0) {
            prow[j0] = (j0 == i) ? 0.f : fmaxf(acc0 + bias, 0.f);
            mrow[j0] = (j0 == i) ? 0.f : 1.f;
            if (p1) { prow[j1] = (j1 == i) ? 0.f : fmaxf(acc1 + bias, 0.f);
                      mrow[j1] = (j1 == i) ? 0.f : 1.f; }
            if (p2) { prow[j2] = (j2 == i) ? 0.f : fmaxf(acc2 + bias, 0.f);
                      mrow[j2] = (j2 == i) ? 0.f : 1.f; }
            if (p3) { prow[j3] = (j3 == i) ? 0.f : fmaxf(acc3 + bias, 0.f);
                      mrow[j3] = (j3 == i) ? 0.f : 1.f; }
        }
    }
}

extern "C" void kernel_launch(void* const* d_in, const int* in_sizes, int n_in,
                              void* d_out, int out_size)
{
    const float* xs    = (const float*)d_in[0];  // [1024, 256] f32
    const int*   batch = (const int*)d_in[1];    // [1024] int32 (sorted, ids in [0,32))
    const float* w     = (const float*)d_in[2];  // [256] f32
    const float* b     = (const float*)d_in[3];  // [1] f32

    float* out       = (float*)d_out;
    float* out_pred  = out;                              // [1024*1024]
    float* out_mask  = out + (size_t)NROWS * NROWS;      // [1024*1024]
    float* out_count = out + 2 * (size_t)NROWS * NROWS;  // [1]

    distmax_fused<<<NROWS + 1, 256>>>(xs, batch, w, b, out_pred, out_mask, out_count);
}

// round 6
// speedup vs baseline: 1.3434x; 1.0025x over previous
#include <cuda_runtime.h>

#define NROWS 1024
#define EMB   256

// Precomputed per-row same-graph segment bounds [lo, hi).
__device__ int2 g_bounds[NROWS];

// Kernel A (1 CTA, 1024 threads): histogram of batch (32 graph ids),
// shfl prefix-sum -> per-row bounds; count = sum_g h_g^2 - N (exact).
__global__ __launch_bounds__(1024) void distmax_setup(
    const int* __restrict__ batch, float* __restrict__ out_count)
{
    __shared__ int h[32];
    __shared__ int st[33];
    const int t = threadIdx.x;
    if (t < 32) h[t] = 0;
    __syncthreads();
    const int g = batch[t];
    atomicAdd(&h[g], 1);
    __syncthreads();
    if (t < 32) {
        const int v = h[t];
        int c = v * v;
        #pragma unroll
        for (int o = 16; o; o >>= 1) c += __shfl_xor_sync(0xffffffffu, c, o);
        if (t == 0) out_count[0] = (float)(c - NROWS);
        // inclusive prefix sum of h -> st[t+1]
        int x = v;
        #pragma unroll
        for (int o = 1; o < 32; o <<= 1) {
            int y = __shfl_up_sync(0xffffffffu, x, o);
            if (t >= o) x += y;
        }
        st[t + 1] = x;
        if (t == 0) st[0] = 0;
    }
    __syncthreads();
    g_bounds[t] = make_int2(st[g], st[g + 1]);
}

// Kernel B: one CTA (128 threads, 4 warps) per row i. No scan, no barrier.
//   zero phase: each thread owns 8 columns; writes zeros only OUTSIDE [lo,hi).
//   compute phase: warp-per-j over [lo,hi), 4-way unrolled, writes every
//   interior column (diagonal as 0). Writes are disjoint -> barrier-free.
__global__ __launch_bounds__(128) void distmax_rows(
    const float* __restrict__ xs,
    const float* __restrict__ w, const float* __restrict__ bptr,
    float* __restrict__ out_pred, float* __restrict__ out_mask)
{
    const int i    = blockIdx.x;
    const int t    = threadIdx.x;
    const int lane = t & 31;
    const int wid  = t >> 5;

    const int2 bb = g_bounds[i];
    const int lo = bb.x, hi = bb.y;

    const size_t rowoff = (size_t)i * NROWS;
    float* __restrict__ prow = out_pred + rowoff;
    float* __restrict__ mrow = out_mask + rowoff;

    // ---- zero exterior: thread t covers cols [t*8, t*8+8) as 2 float4 ----
    {
        const float4 z = make_float4(0.f, 0.f, 0.f, 0.f);
        #pragma unroll
        for (int half = 0; half < 2; half++) {
            const int c0 = t * 8 + half * 4;
            if (c0 + 4 <= lo || c0 >= hi) {
                reinterpret_cast<float4*>(prow)[c0 >> 2] = z;
                reinterpret_cast<float4*>(mrow)[c0 >> 2] = z;
            } else if (c0 < lo || c0 + 4 > hi) {
                #pragma unroll
                for (int e = 0; e < 4; e++) {
                    const int c = c0 + e;
                    if (c < lo || c >= hi) { prow[c] = 0.f; mrow[c] = 0.f; }
                }
            }
        }
    }

    // ---- compute interior: warp-per-j, 4-way unrolled (stride 16) ----
    const float bias = __ldg(bptr);
    const float4* xi4 = reinterpret_cast<const float4*>(xs + (size_t)i * EMB);
    const float4* w4  = reinterpret_cast<const float4*>(w);
    const float4 xi0 = xi4[lane * 2], xi1 = xi4[lane * 2 + 1];
    const float4 w0  = w4 [lane * 2], w1  = w4 [lane * 2 + 1];

    for (int jb = lo + wid; jb < hi; jb += 16) {
        const int j0 = jb, j1 = jb + 4, j2 = jb + 8, j3 = jb + 12;
        const bool p1 = (j1 < hi), p2 = (j2 < hi), p3 = (j3 < hi);

        float acc0 = 0.f, acc1 = 0.f, acc2 = 0.f, acc3 = 0.f;
        {
            const float4* xj = reinterpret_cast<const float4*>(xs + (size_t)j0 * EMB);
            const float4 a = xj[lane * 2], b = xj[lane * 2 + 1];
            acc0 = fmaf(fmaxf(xi0.x, a.x), w0.x,
                   fmaf(fmaxf(xi0.y, a.y), w0.y,
                   fmaf(fmaxf(xi0.z, a.z), w0.z,
                   fmaf(fmaxf(xi0.w, a.w), w0.w,
                   fmaf(fmaxf(xi1.x, b.x), w1.x,
                   fmaf(fmaxf(xi1.y, b.y), w1.y,
                   fmaf(fmaxf(xi1.z, b.z), w1.z,
                        fmaxf(xi1.w, b.w) * w1.w)))))));
        }
        if (p1) {
            const float4* xj = reinterpret_cast<const float4*>(xs + (size_t)j1 * EMB);
            const float4 a = xj[lane * 2], b = xj[lane * 2 + 1];
            acc1 = fmaf(fmaxf(xi0.x, a.x), w0.x,
                   fmaf(fmaxf(xi0.y, a.y), w0.y,
                   fmaf(fmaxf(xi0.z, a.z), w0.z,
                   fmaf(fmaxf(xi0.w, a.w), w0.w,
                   fmaf(fmaxf(xi1.x, b.x), w1.x,
                   fmaf(fmaxf(xi1.y, b.y), w1.y,
                   fmaf(fmaxf(xi1.z, b.z), w1.z,
                        fmaxf(xi1.w, b.w) * w1.w)))))));
        }
        if (p2) {
            const float4* xj = reinterpret_cast<const float4*>(xs + (size_t)j2 * EMB);
            const float4 a = xj[lane * 2], b = xj[lane * 2 + 1];
            acc2 = fmaf(fmaxf(xi0.x, a.x), w0.x,
                   fmaf(fmaxf(xi0.y, a.y), w0.y,
                   fmaf(fmaxf(xi0.z, a.z), w0.z,
                   fmaf(fmaxf(xi0.w, a.w), w0.w,
                   fmaf(fmaxf(xi1.x, b.x), w1.x,
                   fmaf(fmaxf(xi1.y, b.y), w1.y,
                   fmaf(fmaxf(xi1.z, b.z), w1.z,
                        fmaxf(xi1.w, b.w) * w1.w)))))));
        }
        if (p3) {
            const float4* xj = reinterpret_cast<const float4*>(xs + (size_t)j3 * EMB);
            const float4 a = xj[lane * 2], b = xj[lane * 2 + 1];
            acc3 = fmaf(fmaxf(xi0.x, a.x), w0.x,
                   fmaf(fmaxf(xi0.y, a.y), w0.y,
                   fmaf(fmaxf(xi0.z, a.z), w0.z,
                   fmaf(fmaxf(xi0.w, a.w), w0.w,
                   fmaf(fmaxf(xi1.x, b.x), w1.x,
                   fmaf(fmaxf(xi1.y, b.y), w1.y,
                   fmaf(fmaxf(xi1.z, b.z), w1.z,
                        fmaxf(xi1.w, b.w) * w1.w)))))));
        }

        #pragma unroll
        for (int o = 16; o; o >>= 1) {
            acc0 += __shfl_xor_sync(0xffffffffu, acc0, o);
            acc1 += __shfl_xor_sync(0xffffffffu, acc1, o);
            acc2 += __shfl_xor_sync(0xffffffffu, acc2, o);
            acc3 += __shfl_xor_sync(0xffffffffu, acc3, o);
        }

        if (lane == 0) {
            prow[j0] = (j0 == i) ? 0.f : fmaxf(acc0 + bias, 0.f);
            mrow[j0] = (j0 == i) ? 0.f : 1.f;
            if (p1) { prow[j1] = (j1 == i) ? 0.f : fmaxf(acc1 + bias, 0.f);
                      mrow[j1] = (j1 == i) ? 0.f : 1.f; }
            if (p2) { prow[j2] = (j2 == i) ? 0.f : fmaxf(acc2 + bias, 0.f);
                      mrow[j2] = (j2 == i) ? 0.f : 1.f; }
            if (p3) { prow[j3] = (j3 == i) ? 0.f : fmaxf(acc3 + bias, 0.f);
                      mrow[j3] = (j3 == i) ? 0.f : 1.f; }
        }
    }
}

extern "C" void kernel_launch(void* const* d_in, const int* in_sizes, int n_in,
                              void* d_out, int out_size)
{
    const float* xs    = (const float*)d_in[0];  // [1024, 256] f32
    const int*   batch = (const int*)d_in[1];    // [1024] int32 (sorted, ids in [0,32))
    const float* w     = (const float*)d_in[2];  // [256] f32
    const float* b     = (const float*)d_in[3];  // [1] f32

    float* out       = (float*)d_out;
    float* out_pred  = out;                              // [1024*1024]
    float* out_mask  = out + (size_t)NROWS * NROWS;      // [1024*1024]
    float* out_count = out + 2 * (size_t)NROWS * NROWS;  // [1]

    distmax_setup<<<1, 1024>>>(batch, out_count);
    distmax_rows<<<NROWS, 128>>>(xs, w, b, out_pred, out_mask);
}

// round 7
// speedup vs baseline: 1.4605x; 1.0872x over previous
#include <cuda_runtime.h>

#define NROWS 1024
#define EMB   256
#define WIN   384   // window elements (must be multiple of 128; covers group always)

// One kernel. Row CTAs (blockIdx.x < NROWS): 128 threads, barrier-free.
//   Each warp: windowed count around i -> [lo,hi); zero exterior cols;
//   compute interior warp-per-j 4-way unrolled (diagonal 0).
// Count CTA (blockIdx.x == NROWS): 32-bin histogram; count = sum h^2 - N.
__global__ __launch_bounds__(128) void distmax_all(
    const float* __restrict__ xs, const int* __restrict__ batch,
    const float* __restrict__ w, const float* __restrict__ bptr,
    float* __restrict__ out_pred, float* __restrict__ out_mask,
    float* __restrict__ out_count)
{
    const int t    = threadIdx.x;
    const int lane = t & 31;
    const int wid  = t >> 5;

    // ---- count CTA ----
    if (blockIdx.x == NROWS) {
        __shared__ int h[32];
        if (t < 32) h[t] = 0;
        __syncthreads();
        #pragma unroll
        for (int k = 0; k < 2; k++) {
            int4 v = reinterpret_cast<const int4*>(batch)[t + k * 128];
            atomicAdd(&h[v.x], 1);
            atomicAdd(&h[v.y], 1);
            atomicAdd(&h[v.z], 1);
            atomicAdd(&h[v.w], 1);
        }
        __syncthreads();
        if (t < 32) {
            int c = h[t] * h[t];
            #pragma unroll
            for (int o = 16; o; o >>= 1) c += __shfl_xor_sync(0xffffffffu, c, o);
            if (t == 0) out_count[0] = (float)(c - NROWS);
        }
        return;
    }

    const int i = blockIdx.x;

    // ---- windowed bounds: each warp independently (no barrier) ----
    // window [wbase, wbase+WIN) aligned to int4, clamped, always contains
    // the whole group of row i (group size << WIN/2).
    int wbase = i - WIN / 2;
    if (wbase < 0) wbase = 0;
    wbase &= ~3;
    if (wbase > NROWS - WIN) wbase = NROWS - WIN;

    const int bi = __ldg(batch + i);
    int nbefore = 0, nafter = 0;
    const int4* b4 = reinterpret_cast<const int4*>(batch + wbase);
    #pragma unroll
    for (int k = 0; k < WIN / 128; k++) {
        const int4 v = b4[k * 32 + lane];
        const int g0 = wbase + (k * 32 + lane) * 4;
        nbefore += (v.x == bi && g0     < i) + (v.y == bi && g0 + 1 < i)
                 + (v.z == bi && g0 + 2 < i) + (v.w == bi && g0 + 3 < i);
        nafter  += (v.x == bi && g0     > i) + (v.y == bi && g0 + 1 > i)
                 + (v.z == bi && g0 + 2 > i) + (v.w == bi && g0 + 3 > i);
    }
    #pragma unroll
    for (int o = 16; o; o >>= 1) {
        nbefore += __shfl_xor_sync(0xffffffffu, nbefore, o);
        nafter  += __shfl_xor_sync(0xffffffffu, nafter,  o);
    }
    const int lo = i - nbefore;
    const int hi = i + nafter + 1;

    const size_t rowoff = (size_t)i * NROWS;
    float* __restrict__ prow = out_pred + rowoff;
    float* __restrict__ mrow = out_mask + rowoff;

    // ---- zero exterior: thread t covers cols [t*8, t*8+8) as 2 float4 ----
    {
        const float4 z = make_float4(0.f, 0.f, 0.f, 0.f);
        #pragma unroll
        for (int half = 0; half < 2; half++) {
            const int c0 = t * 8 + half * 4;
            if (c0 + 4 <= lo || c0 >= hi) {
                reinterpret_cast<float4*>(prow)[c0 >> 2] = z;
                reinterpret_cast<float4*>(mrow)[c0 >> 2] = z;
            } else if (c0 < lo || c0 + 4 > hi) {
                #pragma unroll
                for (int e = 0; e < 4; e++) {
                    const int c = c0 + e;
                    if (c < lo || c >= hi) { prow[c] = 0.f; mrow[c] = 0.f; }
                }
            }
        }
    }

    // ---- compute interior: warp-per-j, 4-way unrolled (stride 16) ----
    const float bias = __ldg(bptr);
    const float4* xi4 = reinterpret_cast<const float4*>(xs + (size_t)i * EMB);
    const float4* w4  = reinterpret_cast<const float4*>(w);
    const float4 xi0 = xi4[lane * 2], xi1 = xi4[lane * 2 + 1];
    const float4 w0  = w4 [lane * 2], w1  = w4 [lane * 2 + 1];

    for (int jb = lo + wid; jb < hi; jb += 16) {
        const int j0 = jb, j1 = jb + 4, j2 = jb + 8, j3 = jb + 12;
        const bool p1 = (j1 < hi), p2 = (j2 < hi), p3 = (j3 < hi);

        float acc0 = 0.f, acc1 = 0.f, acc2 = 0.f, acc3 = 0.f;
        {
            const float4* xj = reinterpret_cast<const float4*>(xs + (size_t)j0 * EMB);
            const float4 a = xj[lane * 2], b = xj[lane * 2 + 1];
            acc0 = fmaf(fmaxf(xi0.x, a.x), w0.x,
                   fmaf(fmaxf(xi0.y, a.y), w0.y,
                   fmaf(fmaxf(xi0.z, a.z), w0.z,
                   fmaf(fmaxf(xi0.w, a.w), w0.w,
                   fmaf(fmaxf(xi1.x, b.x), w1.x,
                   fmaf(fmaxf(xi1.y, b.y), w1.y,
                   fmaf(fmaxf(xi1.z, b.z), w1.z,
                        fmaxf(xi1.w, b.w) * w1.w)))))));
        }
        if (p1) {
            const float4* xj = reinterpret_cast<const float4*>(xs + (size_t)j1 * EMB);
            const float4 a = xj[lane * 2], b = xj[lane * 2 + 1];
            acc1 = fmaf(fmaxf(xi0.x, a.x), w0.x,
                   fmaf(fmaxf(xi0.y, a.y), w0.y,
                   fmaf(fmaxf(xi0.z, a.z), w0.z,
                   fmaf(fmaxf(xi0.w, a.w), w0.w,
                   fmaf(fmaxf(xi1.x, b.x), w1.x,
                   fmaf(fmaxf(xi1.y, b.y), w1.y,
                   fmaf(fmaxf(xi1.z, b.z), w1.z,
                        fmaxf(xi1.w, b.w) * w1.w)))))));
        }
        if (p2) {
            const float4* xj = reinterpret_cast<const float4*>(xs + (size_t)j2 * EMB);
            const float4 a = xj[lane * 2], b = xj[lane * 2 + 1];
            acc2 = fmaf(fmaxf(xi0.x, a.x), w0.x,
                   fmaf(fmaxf(xi0.y, a.y), w0.y,
                   fmaf(fmaxf(xi0.z, a.z), w0.z,
                   fmaf(fmaxf(xi0.w, a.w), w0.w,
                   fmaf(fmaxf(xi1.x, b.x), w1.x,
                   fmaf(fmaxf(xi1.y, b.y), w1.y,
                   fmaf(fmaxf(xi1.z, b.z), w1.z,
                        fmaxf(xi1.w, b.w) * w1.w)))))));
        }
        if (p3) {
            const float4* xj = reinterpret_cast<const float4*>(xs + (size_t)j3 * EMB);
            const float4 a = xj[lane * 2], b = xj[lane * 2 + 1];
            acc3 = fmaf(fmaxf(xi0.x, a.x), w0.x,
                   fmaf(fmaxf(xi0.y, a.y), w0.y,
                   fmaf(fmaxf(xi0.z, a.z), w0.z,
                   fmaf(fmaxf(xi0.w, a.w), w0.w,
                   fmaf(fmaxf(xi1.x, b.x), w1.x,
                   fmaf(fmaxf(xi1.y, b.y), w1.y,
                   fmaf(fmaxf(xi1.z, b.z), w1.z,
                        fmaxf(xi1.w, b.w) * w1.w)))))));
        }

        #pragma unroll
        for (int o = 16; o; o >>= 1) {
            acc0 += __shfl_xor_sync(0xffffffffu, acc0, o);
            acc1 += __shfl_xor_sync(0xffffffffu, acc1, o);
            acc2 += __shfl_xor_sync(0xffffffffu, acc2, o);
            acc3 += __shfl_xor_sync(0xffffffffu, acc3, o);
        }

        if (lane == 0) {
            prow[j0] = (j0 == i) ? 0.f : fmaxf(acc0 + bias, 0.f);
            mrow[j0] = (j0 == i) ? 0.f : 1.f;
            if (p1) { prow[j1] = (j1 == i) ? 0.f : fmaxf(acc1 + bias, 0.f);
                      mrow[j1] = (j1 == i) ? 0.f : 1.f; }
            if (p2) { prow[j2] = (j2 == i) ? 0.f : fmaxf(acc2 + bias, 0.f);
                      mrow[j2] = (j2 == i) ? 0.f : 1.f; }
            if (p3) { prow[j3] = (j3 == i) ? 0.f : fmaxf(acc3 + bias, 0.f);
                      mrow[j3] = (j3 == i) ? 0.f : 1.f; }
        }
    }
}

extern "C" void kernel_launch(void* const* d_in, const int* in_sizes, int n_in,
                              void* d_out, int out_size)
{
    const float* xs    = (const float*)d_in[0];  // [1024, 256] f32
    const int*   batch = (const int*)d_in[1];    // [1024] int32 (sorted, ids in [0,32))
    const float* w     = (const float*)d_in[2];  // [256] f32
    const float* b     = (const float*)d_in[3];  // [1] f32

    float* out       = (float*)d_out;
    float* out_pred  = out;                              // [1024*1024]
    float* out_mask  = out + (size_t)NROWS * NROWS;      // [1024*1024]
    float* out_count = out + 2 * (size_t)NROWS * NROWS;  // [1]

    distmax_all<<<NROWS + 1, 128>>>(xs, batch, w, b, out_pred, out_mask, out_count);
}